// round 9
// baseline (speedup 1.0000x reference)
#include <cuda_runtime.h>
#include <cuda_fp16.h>
#include <cfloat>
#include <math.h>
#include <cstdint>
#include <mma.h>

using namespace nvcuda;

// Problem constants
#define NN   20000
#define NE   320000
#define HC   512
#define NH   4
#define OC   128
#define KDIM 512
#define NDIM 512
#define ETOT (NE + NN)    // edges + self-loops

// -------- scratch --------
__device__ __half g_xh[(size_t)NN * KDIM];    // x, fp16
__device__ __half g_wh[(size_t)KDIM * NDIM];  // W, fp16
__device__ __half g_xlh[(size_t)NN * HC];     // projected features, fp16
__device__ float  g_as[NN * NH];
__device__ float  g_ad[NN * NH];
__device__ int    g_deg[NN];                  // in-degree histogram
__device__ int    g_off[NN + 1];              // CSR offsets
__device__ int    g_cur[NN];                  // fill cursors
__device__ int    g_csrc[ETOT];               // CSR: src per (dst-sorted) edge

// ---------------- fp16 pre-conversion of x and W + zero histogram -------
__global__ void k_cvt(const float* __restrict__ x, const float* __restrict__ W) {
    const int totx = NN * KDIM / 4;
    const int totw = KDIM * NDIM / 4;
    int i = blockIdx.x * blockDim.x + threadIdx.x;
    if (i < NN) g_deg[i] = 0;
    if (i < totx) {
        float4 v = ((const float4*)x)[i];
        union { uint2 u; __half2 h[2]; } pk;
        pk.h[0] = __floats2half2_rn(v.x, v.y);
        pk.h[1] = __floats2half2_rn(v.z, v.w);
        ((uint2*)g_xh)[i] = pk.u;
    } else if (i < totx + totw) {
        int j = i - totx;
        float4 v = ((const float4*)W)[j];
        union { uint2 u; __half2 h[2]; } pk;
        pk.h[0] = __floats2half2_rn(v.x, v.y);
        pk.h[1] = __floats2half2_rn(v.z, v.w);
        ((uint2*)g_wh)[j] = pk.u;
    }
}

// ---------------- CSR build ----------------
__global__ void k_hist(const int* __restrict__ ei) {
    int e = blockIdx.x * blockDim.x + threadIdx.x;
    if (e >= ETOT) return;
    int dst = (e < NE) ? ei[NE + e] : e - NE;
    atomicAdd(&g_deg[dst], 1);
}

// single block, 1024 threads: exclusive prefix sum of g_deg -> g_off, g_cur
__global__ __launch_bounds__(1024) void k_scan() {
    __shared__ int part[1024];
    const int t = threadIdx.x;
    const int CH = (NN + 1023) / 1024;   // 20
    int loc[CH];
    int base = t * CH;
    int s = 0;
    #pragma unroll
    for (int i = 0; i < CH; i++) {
        int idx = base + i;
        loc[i] = (idx < NN) ? g_deg[idx] : 0;
        s += loc[i];
    }
    part[t] = s;
    __syncthreads();
    // inclusive Hillis-Steele scan over 1024 partials
    #pragma unroll
    for (int off = 1; off < 1024; off <<= 1) {
        int v = (t >= off) ? part[t - off] : 0;
        __syncthreads();
        part[t] += v;
        __syncthreads();
    }
    int run = part[t] - s;   // exclusive prefix of this chunk
    #pragma unroll
    for (int i = 0; i < CH; i++) {
        int idx = base + i;
        if (idx < NN) {
            g_off[idx] = run;
            g_cur[idx] = run;
            run += loc[i];
        }
    }
    if (t == 1023) g_off[NN] = part[1023];
}

__global__ void k_permute(const int* __restrict__ ei) {
    int e = blockIdx.x * blockDim.x + threadIdx.x;
    if (e >= ETOT) return;
    int src, dst;
    if (e < NE) { src = ei[e]; dst = ei[NE + e]; }
    else        { src = dst = e - NE; }
    int pos = atomicAdd(&g_cur[dst], 1);
    g_csrc[pos] = src;
}

// ---------------- GEMM (fp16 wmma 16x16x16) + fused epilogue -------------
#define BLK_K  64
#define LDA_H  72
#define LDB_H  136
#define A_HALFS (128 * LDA_H)
#define B_HALFS (BLK_K * LDB_H)
#define STAGE_HALFS (A_HALFS + B_HALFS)
#define NSTAGE 3
#define GEMM_SMEM (NSTAGE * STAGE_HALFS * 2)
#define LDC 132

__device__ __forceinline__ uint32_t smem_u32(const void* p) {
    uint32_t a;
    asm("{ .reg .u64 t; cvta.to.shared.u64 t, %1; cvt.u32.u64 %0, t; }" : "=r"(a) : "l"(p));
    return a;
}

__global__ __launch_bounds__(256) void k_gemm_tc(const float* __restrict__ att_src,
                                                 const float* __restrict__ att_dst) {
    extern __shared__ __half smemh[];
    __half* As = smemh;
    __half* Bs = smemh + NSTAGE * A_HALFS;

    const int tid = threadIdx.x;
    const int warpId = tid >> 5;
    const int lane = tid & 31;
    const int warpM = warpId & 3;
    const int warpN = warpId >> 2;
    const int m0 = blockIdx.y * 128;
    const int n0 = blockIdx.x * 128;

    const uint32_t sA = smem_u32(As);
    const uint32_t sB = smem_u32(Bs);

    auto load_stage = [&](int kc, int buf) {
        const int k0 = kc * BLK_K;
        #pragma unroll
        for (int it = 0; it < 4; it++) {
            int id = tid + it * 256;
            int r = id >> 3, q = id & 7;
            int grow = m0 + r;
            const __half* gp = g_xh + (size_t)(grow < NN ? grow : 0) * KDIM + k0 + q * 8;
            int sz = (grow < NN) ? 16 : 0;
            uint32_t so = sA + (buf * A_HALFS + r * LDA_H + q * 8) * 2;
            asm volatile("cp.async.cg.shared.global [%0], [%1], 16, %2;"
                         :: "r"(so), "l"(gp), "r"(sz));
        }
        #pragma unroll
        for (int it = 0; it < 4; it++) {
            int id = tid + it * 256;
            int r = id >> 4, q = id & 15;
            const __half* gp = g_wh + (size_t)(k0 + r) * NDIM + n0 + q * 8;
            uint32_t so = sB + (buf * B_HALFS + r * LDB_H + q * 8) * 2;
            asm volatile("cp.async.cg.shared.global [%0], [%1], 16;"
                         :: "r"(so), "l"(gp));
        }
        asm volatile("cp.async.commit_group;" ::: "memory");
    };

    wmma::fragment<wmma::accumulator, 16, 16, 16, float> acc[2][4];
    #pragma unroll
    for (int i = 0; i < 2; i++)
        #pragma unroll
        for (int j = 0; j < 4; j++) wmma::fill_fragment(acc[i][j], 0.f);

    load_stage(0, 0);
    load_stage(1, 1);

    const int NCHUNK = KDIM / BLK_K;   // 8
    for (int kc = 0; kc < NCHUNK; kc++) {
        const int buf = kc % NSTAGE;
        if (kc + 1 < NCHUNK)
            asm volatile("cp.async.wait_group 1;" ::: "memory");
        else
            asm volatile("cp.async.wait_group 0;" ::: "memory");
        __syncthreads();
        if (kc + 2 < NCHUNK) load_stage(kc + 2, (kc + 2) % NSTAGE);

        const __half* Ab = As + buf * A_HALFS + warpM * 32 * LDA_H;
        const __half* Bb = Bs + buf * B_HALFS + warpN * 64;
        #pragma unroll
        for (int ks = 0; ks < BLK_K / 16; ks++) {
            wmma::fragment<wmma::matrix_a, 16, 16, 16, __half, wmma::row_major> af[2];
            wmma::fragment<wmma::matrix_b, 16, 16, 16, __half, wmma::row_major> bf[4];
            #pragma unroll
            for (int mt = 0; mt < 2; mt++)
                wmma::load_matrix_sync(af[mt], Ab + mt * 16 * LDA_H + ks * 16, LDA_H);
            #pragma unroll
            for (int nt = 0; nt < 4; nt++)
                wmma::load_matrix_sync(bf[nt], Bb + ks * 16 * LDB_H + nt * 16, LDB_H);
            #pragma unroll
            for (int mt = 0; mt < 2; mt++)
                #pragma unroll
                for (int nt = 0; nt < 4; nt++)
                    wmma::mma_sync(acc[mt][nt], af[mt], bf[nt], acc[mt][nt]);
        }
    }

    // -------- fused epilogue: attn halves + fp16 store --------
    __syncthreads();
    float* Cs = (float*)smemh;
    #pragma unroll
    for (int mt = 0; mt < 2; mt++)
        #pragma unroll
        for (int nt = 0; nt < 4; nt++)
            wmma::store_matrix_sync(Cs + (warpM * 32 + mt * 16) * LDC + warpN * 64 + nt * 16,
                                    acc[mt][nt], LDC, wmma::mem_row_major);
    __syncthreads();

    const int h = blockIdx.x;
    float4 sv = *(const float4*)(att_src + h * OC + lane * 4);
    float4 dv = *(const float4*)(att_dst + h * OC + lane * 4);

    #pragma unroll
    for (int r = 0; r < 16; r++) {
        int lrow = warpId * 16 + r;
        int grow = m0 + lrow;
        float4 v = *(const float4*)(Cs + lrow * LDC + lane * 4);
        float ss = v.x * sv.x + v.y * sv.y + v.z * sv.z + v.w * sv.w;
        float dd = v.x * dv.x + v.y * dv.y + v.z * dv.z + v.w * dv.w;
        #pragma unroll
        for (int o = 16; o; o >>= 1) {
            ss += __shfl_xor_sync(0xFFFFFFFFu, ss, o);
            dd += __shfl_xor_sync(0xFFFFFFFFu, dd, o);
        }
        if (grow < NN) {
            union { uint2 u; __half2 hh[2]; } pk;
            pk.hh[0] = __floats2half2_rn(v.x, v.y);
            pk.hh[1] = __floats2half2_rn(v.z, v.w);
            *(uint2*)(g_xlh + (size_t)grow * HC + h * OC + lane * 4) = pk.u;
            if (lane == 0) {
                g_as[grow * NH + h] = ss;
                g_ad[grow * NH + h] = dd;
            }
        }
    }
}

__device__ __forceinline__ float leaky(float a) { return a > 0.f ? a : 0.2f * a; }

// ---------------- fused gather: softmax + weighted sum + mean/bias/elu --
// warp per dst node; no atomics, out written exactly once.
__global__ __launch_bounds__(256) void k_gather(float* __restrict__ out,
                                                const float* __restrict__ bias) {
    int w    = (blockIdx.x * blockDim.x + threadIdx.x) >> 5;
    int lane = threadIdx.x & 31;
    if (w >= NN) return;
    const int beg = g_off[w], end = g_off[w + 1];

    // dst halves for all 4 heads, broadcast
    float adh = (lane < 4) ? g_ad[w * NH + lane] : 0.f;
    float ad0 = __shfl_sync(0xFFFFFFFFu, adh, 0);
    float ad1 = __shfl_sync(0xFFFFFFFFu, adh, 1);
    float ad2 = __shfl_sync(0xFFFFFFFFu, adh, 2);
    float ad3 = __shfl_sync(0xFFFFFFFFu, adh, 3);

    // pass 1: denominators (lane-parallel over edges)
    float d0 = 0.f, d1 = 0.f, d2 = 0.f, d3 = 0.f;
    for (int p = beg + lane; p < end; p += 32) {
        int s = __ldg(&g_csrc[p]);
        float4 as = *(const float4*)&g_as[s * NH];
        d0 += expf(leaky(as.x + ad0));
        d1 += expf(leaky(as.y + ad1));
        d2 += expf(leaky(as.z + ad2));
        d3 += expf(leaky(as.w + ad3));
    }
    #pragma unroll
    for (int o = 16; o; o >>= 1) {
        d0 += __shfl_xor_sync(0xFFFFFFFFu, d0, o);
        d1 += __shfl_xor_sync(0xFFFFFFFFu, d1, o);
        d2 += __shfl_xor_sync(0xFFFFFFFFu, d2, o);
        d3 += __shfl_xor_sync(0xFFFFFFFFu, d3, o);
    }
    float inv0 = 1.f / (d0 + 1e-16f);
    float inv1 = 1.f / (d1 + 1e-16f);
    float inv2 = 1.f / (d2 + 1e-16f);
    float inv3 = 1.f / (d3 + 1e-16f);

    // pass 2: weighted gather (warp walks edges together)
    float4 r = make_float4(0.f, 0.f, 0.f, 0.f);
    for (int p = beg; p < end; p++) {
        int s = __ldg(&g_csrc[p]);
        // lanes 0-3 compute per-head weight, then broadcast
        float wgt = 0.f;
        if (lane < 4) {
            float inv = (lane == 0) ? inv0 : (lane == 1) ? inv1 : (lane == 2) ? inv2 : inv3;
            wgt = expf(leaky(g_as[s * NH + lane] + adh)) * inv;
        }
        float w0 = __shfl_sync(0xFFFFFFFFu, wgt, 0);
        float w1 = __shfl_sync(0xFFFFFFFFu, wgt, 1);
        float w2 = __shfl_sync(0xFFFFFFFFu, wgt, 2);
        float w3 = __shfl_sync(0xFFFFFFFFu, wgt, 3);

        const uint2* xr = (const uint2*)(g_xlh + (size_t)s * HC);
        uint2 q0 = __ldg(&xr[lane]);
        uint2 q1 = __ldg(&xr[32 + lane]);
        uint2 q2 = __ldg(&xr[64 + lane]);
        uint2 q3 = __ldg(&xr[96 + lane]);
        {
            float2 f0 = __half22float2(*(__half2*)&q0.x);
            float2 f1 = __half22float2(*(__half2*)&q0.y);
            r.x += w0 * f0.x; r.y += w0 * f0.y; r.z += w0 * f1.x; r.w += w0 * f1.y;
        }
        {
            float2 f0 = __half22float2(*(__half2*)&q1.x);
            float2 f1 = __half22float2(*(__half2*)&q1.y);
            r.x += w1 * f0.x; r.y += w1 * f0.y; r.z += w1 * f1.x; r.w += w1 * f1.y;
        }
        {
            float2 f0 = __half22float2(*(__half2*)&q2.x);
            float2 f1 = __half22float2(*(__half2*)&q2.y);
            r.x += w2 * f0.x; r.y += w2 * f0.y; r.z += w2 * f1.x; r.w += w2 * f1.y;
        }
        {
            float2 f0 = __half22float2(*(__half2*)&q3.x);
            float2 f1 = __half22float2(*(__half2*)&q3.y);
            r.x += w3 * f0.x; r.y += w3 * f0.y; r.z += w3 * f1.x; r.w += w3 * f1.y;
        }
    }

    // head mean + bias + elu, single store
    float4 b = *(const float4*)&bias[lane * 4];
    float4 v;
    v.x = r.x * 0.25f + b.x;
    v.y = r.y * 0.25f + b.y;
    v.z = r.z * 0.25f + b.z;
    v.w = r.w * 0.25f + b.w;
    v.x = v.x > 0.f ? v.x : expm1f(v.x);
    v.y = v.y > 0.f ? v.y : expm1f(v.y);
    v.z = v.z > 0.f ? v.z : expm1f(v.z);
    v.w = v.w > 0.f ? v.w : expm1f(v.w);
    *(float4*)&out[(size_t)w * OC + lane * 4] = v;
}

// ========================================================================
extern "C" void kernel_launch(void* const* d_in, const int* in_sizes, int n_in,
                              void* d_out, int out_size) {
    const float* x       = (const float*)d_in[0];
    const float* W       = (const float*)d_in[1];
    const float* att_src = (const float*)d_in[2];
    const float* att_dst = (const float*)d_in[3];
    const float* bias    = (const float*)d_in[4];
    const int*   ei      = (const int*)d_in[5];
    float* out = (float*)d_out;

    cudaFuncSetAttribute(k_gemm_tc, cudaFuncAttributeMaxDynamicSharedMemorySize,
                         GEMM_SMEM);

    // fp16 conversion + histogram zero
    const int cvt_tot = (NN * KDIM + KDIM * NDIM) / 4;
    k_cvt<<<(cvt_tot + 255) / 256, 256>>>(x, W);

    // CSR build (overlappable with GEMM dependencies, but stream-serial is fine)
    k_hist<<<(ETOT + 255) / 256, 256>>>(ei);
    k_scan<<<1, 1024>>>();
    k_permute<<<(ETOT + 255) / 256, 256>>>(ei);

    // GEMM + fused attn epilogue
    dim3 ggrid(NDIM / 128, (NN + 127) / 128);   // (4, 157)
    k_gemm_tc<<<ggrid, 256, GEMM_SMEM>>>(att_src, att_dst);

    // fused softmax + gather + finalize
    k_gather<<<(NN * 32 + 255) / 256, 256>>>(out, bias);
}

// round 10
// speedup vs baseline: 1.3087x; 1.3087x over previous
#include <cuda_runtime.h>
#include <cuda_fp16.h>
#include <cfloat>
#include <math.h>
#include <cstdint>
#include <mma.h>

using namespace nvcuda;

// Problem constants
#define NN   20000
#define NE   320000
#define HC   512
#define NH   4
#define OC   128
#define KDIM 512
#define NDIM 512
#define ETOT (NE + NN)   // 340000 (even)

// -------- scratch --------
__device__ __half g_xh[(size_t)NN * KDIM];    // x, fp16
__device__ __half g_wh[(size_t)KDIM * NDIM];  // W, fp16
__device__ __half g_xlh[(size_t)NN * HC];     // projected features, fp16
__device__ float  g_as[NN * NH];
__device__ float  g_ad[NN * NH];
__device__ float  g_den[NN * NH];

// ---------------- fp16 pre-conversion of x and W ----------------
__global__ void k_cvt(const float* __restrict__ x, const float* __restrict__ W) {
    const int totx = NN * KDIM / 4;
    const int totw = KDIM * NDIM / 4;
    int i = blockIdx.x * blockDim.x + threadIdx.x;
    if (i < totx) {
        float4 v = ((const float4*)x)[i];
        union { uint2 u; __half2 h[2]; } pk;
        pk.h[0] = __floats2half2_rn(v.x, v.y);
        pk.h[1] = __floats2half2_rn(v.z, v.w);
        ((uint2*)g_xh)[i] = pk.u;
    } else if (i < totx + totw) {
        int j = i - totx;
        float4 v = ((const float4*)W)[j];
        union { uint2 u; __half2 h[2]; } pk;
        pk.h[0] = __floats2half2_rn(v.x, v.y);
        pk.h[1] = __floats2half2_rn(v.z, v.w);
        ((uint2*)g_wh)[j] = pk.u;
    }
}

// ---------------- GEMM (fp16 wmma 16x16x16) + fused epilogue -------------
#define BLK_K  64
#define LDA_H  72
#define LDB_H  136
#define A_HALFS (128 * LDA_H)
#define B_HALFS (BLK_K * LDB_H)
#define STAGE_HALFS (A_HALFS + B_HALFS)
#define NSTAGE 3
#define GEMM_SMEM (NSTAGE * STAGE_HALFS * 2)
#define LDC 132

__device__ __forceinline__ uint32_t smem_u32(const void* p) {
    uint32_t a;
    asm("{ .reg .u64 t; cvta.to.shared.u64 t, %1; cvt.u32.u64 %0, t; }" : "=r"(a) : "l"(p));
    return a;
}

__global__ __launch_bounds__(256) void k_gemm_tc(const float* __restrict__ att_src,
                                                 const float* __restrict__ att_dst) {
    extern __shared__ __half smemh[];
    __half* As = smemh;
    __half* Bs = smemh + NSTAGE * A_HALFS;

    const int tid = threadIdx.x;
    const int warpId = tid >> 5;
    const int lane = tid & 31;
    const int warpM = warpId & 3;
    const int warpN = warpId >> 2;
    const int m0 = blockIdx.y * 128;
    const int n0 = blockIdx.x * 128;

    const uint32_t sA = smem_u32(As);
    const uint32_t sB = smem_u32(Bs);

    auto load_stage = [&](int kc, int buf) {
        const int k0 = kc * BLK_K;
        #pragma unroll
        for (int it = 0; it < 4; it++) {
            int id = tid + it * 256;
            int r = id >> 3, q = id & 7;
            int grow = m0 + r;
            const __half* gp = g_xh + (size_t)(grow < NN ? grow : 0) * KDIM + k0 + q * 8;
            int sz = (grow < NN) ? 16 : 0;
            uint32_t so = sA + (buf * A_HALFS + r * LDA_H + q * 8) * 2;
            asm volatile("cp.async.cg.shared.global [%0], [%1], 16, %2;"
                         :: "r"(so), "l"(gp), "r"(sz));
        }
        #pragma unroll
        for (int it = 0; it < 4; it++) {
            int id = tid + it * 256;
            int r = id >> 4, q = id & 15;
            const __half* gp = g_wh + (size_t)(k0 + r) * NDIM + n0 + q * 8;
            uint32_t so = sB + (buf * B_HALFS + r * LDB_H + q * 8) * 2;
            asm volatile("cp.async.cg.shared.global [%0], [%1], 16;"
                         :: "r"(so), "l"(gp));
        }
        asm volatile("cp.async.commit_group;" ::: "memory");
    };

    wmma::fragment<wmma::accumulator, 16, 16, 16, float> acc[2][4];
    #pragma unroll
    for (int i = 0; i < 2; i++)
        #pragma unroll
        for (int j = 0; j < 4; j++) wmma::fill_fragment(acc[i][j], 0.f);

    load_stage(0, 0);
    load_stage(1, 1);

    const int NCHUNK = KDIM / BLK_K;   // 8
    for (int kc = 0; kc < NCHUNK; kc++) {
        const int buf = kc % NSTAGE;
        if (kc + 1 < NCHUNK)
            asm volatile("cp.async.wait_group 1;" ::: "memory");
        else
            asm volatile("cp.async.wait_group 0;" ::: "memory");
        __syncthreads();
        if (kc + 2 < NCHUNK) load_stage(kc + 2, (kc + 2) % NSTAGE);

        const __half* Ab = As + buf * A_HALFS + warpM * 32 * LDA_H;
        const __half* Bb = Bs + buf * B_HALFS + warpN * 64;
        #pragma unroll
        for (int ks = 0; ks < BLK_K / 16; ks++) {
            wmma::fragment<wmma::matrix_a, 16, 16, 16, __half, wmma::row_major> af[2];
            wmma::fragment<wmma::matrix_b, 16, 16, 16, __half, wmma::row_major> bf[4];
            #pragma unroll
            for (int mt = 0; mt < 2; mt++)
                wmma::load_matrix_sync(af[mt], Ab + mt * 16 * LDA_H + ks * 16, LDA_H);
            #pragma unroll
            for (int nt = 0; nt < 4; nt++)
                wmma::load_matrix_sync(bf[nt], Bb + ks * 16 * LDB_H + nt * 16, LDB_H);
            #pragma unroll
            for (int mt = 0; mt < 2; mt++)
                #pragma unroll
                for (int nt = 0; nt < 4; nt++)
                    wmma::mma_sync(acc[mt][nt], af[mt], bf[nt], acc[mt][nt]);
        }
    }

    // -------- fused epilogue: attn halves + fp16 store --------
    __syncthreads();
    float* Cs = (float*)smemh;
    #pragma unroll
    for (int mt = 0; mt < 2; mt++)
        #pragma unroll
        for (int nt = 0; nt < 4; nt++)
            wmma::store_matrix_sync(Cs + (warpM * 32 + mt * 16) * LDC + warpN * 64 + nt * 16,
                                    acc[mt][nt], LDC, wmma::mem_row_major);
    __syncthreads();

    const int h = blockIdx.x;
    float4 sv = *(const float4*)(att_src + h * OC + lane * 4);
    float4 dv = *(const float4*)(att_dst + h * OC + lane * 4);

    #pragma unroll
    for (int r = 0; r < 16; r++) {
        int lrow = warpId * 16 + r;
        int grow = m0 + lrow;
        float4 v = *(const float4*)(Cs + lrow * LDC + lane * 4);
        float ss = v.x * sv.x + v.y * sv.y + v.z * sv.z + v.w * sv.w;
        float dd = v.x * dv.x + v.y * dv.y + v.z * dv.z + v.w * dv.w;
        #pragma unroll
        for (int o = 16; o; o >>= 1) {
            ss += __shfl_xor_sync(0xFFFFFFFFu, ss, o);
            dd += __shfl_xor_sync(0xFFFFFFFFu, dd, o);
        }
        if (grow < NN) {
            union { uint2 u; __half2 hh[2]; } pk;
            pk.hh[0] = __floats2half2_rn(v.x, v.y);
            pk.hh[1] = __floats2half2_rn(v.z, v.w);
            *(uint2*)(g_xlh + (size_t)grow * HC + h * OC + lane * 4) = pk.u;
            if (lane == 0) {
                g_as[grow * NH + h] = ss;
                g_ad[grow * NH + h] = dd;
            }
        }
    }
}

__device__ __forceinline__ float leaky(float a) { return a > 0.f ? a : 0.2f * a; }

// ---------------- segment sum of exp(alpha) (no max shift) --------------
__global__ void k_edge_sum(const int* __restrict__ ei) {
    int i = blockIdx.x * blockDim.x + threadIdx.x;
    const int tot = ETOT * NH;
    if (i >= tot) return;
    int e = i >> 2, h = i & 3;
    int src, dst;
    if (e < NE) { src = ei[e]; dst = ei[NE + e]; }
    else        { src = dst = e - NE; }
    float a = leaky(g_as[src * NH + h] + g_ad[dst * NH + h]);
    atomicAdd(&g_den[dst * NH + h], __expf(a));
}

// ---------------- weighted scatter: 2 edges per warp (fp16 gather) ------
__global__ __launch_bounds__(256) void k_scatter(const int* __restrict__ ei,
                                                 float* __restrict__ out) {
    int w    = (blockIdx.x * blockDim.x + threadIdx.x) >> 5;
    int lane = threadIdx.x & 31;
    if (w >= ETOT / 2) return;
    const int e0 = 2 * w, e1 = e0 + 1;

    int s0, d0, s1, d1;
    if (e0 < NE) { s0 = __ldg(&ei[e0]); d0 = __ldg(&ei[NE + e0]); }
    else         { s0 = d0 = e0 - NE; }
    if (e1 < NE) { s1 = __ldg(&ei[e1]); d1 = __ldg(&ei[NE + e1]); }
    else         { s1 = d1 = e1 - NE; }

    // lanes 0-7: one (edge, head) weight each, fully parallel
    float wt = 0.f;
    if (lane < 8) {
        int es = (lane < 4) ? s0 : s1;
        int ed = (lane < 4) ? d0 : d1;
        int h  = lane & 3;
        float a = leaky(g_as[es * NH + h] + g_ad[ed * NH + h]);
        wt = __expf(a) / (g_den[ed * NH + h] + 1e-16f);
    }
    float w00 = __shfl_sync(0xFFFFFFFFu, wt, 0);
    float w01 = __shfl_sync(0xFFFFFFFFu, wt, 1);
    float w02 = __shfl_sync(0xFFFFFFFFu, wt, 2);
    float w03 = __shfl_sync(0xFFFFFFFFu, wt, 3);
    float w10 = __shfl_sync(0xFFFFFFFFu, wt, 4);
    float w11 = __shfl_sync(0xFFFFFFFFu, wt, 5);
    float w12 = __shfl_sync(0xFFFFFFFFu, wt, 6);
    float w13 = __shfl_sync(0xFFFFFFFFu, wt, 7);

    // 8 independent 256B warp-gathers: maximal MLP before any math
    const uint2* x0 = (const uint2*)(g_xlh + (size_t)s0 * HC);
    const uint2* x1 = (const uint2*)(g_xlh + (size_t)s1 * HC);
    uint2 a0 = __ldg(&x0[lane]);
    uint2 a1 = __ldg(&x0[32 + lane]);
    uint2 a2 = __ldg(&x0[64 + lane]);
    uint2 a3 = __ldg(&x0[96 + lane]);
    uint2 b0 = __ldg(&x1[lane]);
    uint2 b1 = __ldg(&x1[32 + lane]);
    uint2 b2 = __ldg(&x1[64 + lane]);
    uint2 b3 = __ldg(&x1[96 + lane]);

    auto acc4 = [](float4& r, uint2 q, float wgt) {
        float2 f0 = __half22float2(*(__half2*)&q.x);
        float2 f1 = __half22float2(*(__half2*)&q.y);
        r.x += wgt * f0.x; r.y += wgt * f0.y; r.z += wgt * f1.x; r.w += wgt * f1.y;
    };

    float4 r0 = make_float4(0.f, 0.f, 0.f, 0.f);
    acc4(r0, a0, w00); acc4(r0, a1, w01); acc4(r0, a2, w02); acc4(r0, a3, w03);
    float4 r1 = make_float4(0.f, 0.f, 0.f, 0.f);
    acc4(r1, b0, w10); acc4(r1, b1, w11); acc4(r1, b2, w12); acc4(r1, b3, w13);

    float* dp0 = out + (size_t)d0 * OC + lane * 4;
    asm volatile("red.global.add.v4.f32 [%0], {%1, %2, %3, %4};"
                 :: "l"(dp0), "f"(r0.x), "f"(r0.y), "f"(r0.z), "f"(r0.w) : "memory");
    float* dp1 = out + (size_t)d1 * OC + lane * 4;
    asm volatile("red.global.add.v4.f32 [%0], {%1, %2, %3, %4};"
                 :: "l"(dp1), "f"(r1.x), "f"(r1.y), "f"(r1.z), "f"(r1.w) : "memory");
}

// ---------------- finalize ----------------
__global__ void k_final(float* __restrict__ out, const float* __restrict__ bias) {
    int i = blockIdx.x * blockDim.x + threadIdx.x;
    if (i >= NN * OC) return;
    float v = out[i] * 0.25f + bias[i & (OC - 1)];
    out[i] = v > 0.f ? v : expm1f(v);
}

// ========================================================================
extern "C" void kernel_launch(void* const* d_in, const int* in_sizes, int n_in,
                              void* d_out, int out_size) {
    const float* x       = (const float*)d_in[0];
    const float* W       = (const float*)d_in[1];
    const float* att_src = (const float*)d_in[2];
    const float* att_dst = (const float*)d_in[3];
    const float* bias    = (const float*)d_in[4];
    const int*   ei      = (const int*)d_in[5];
    float* out = (float*)d_out;

    cudaFuncSetAttribute(k_gemm_tc, cudaFuncAttributeMaxDynamicSharedMemorySize,
                         GEMM_SMEM);

    // zero accumulators via DMA (graph-capturable async memsets)
    cudaMemsetAsync(out, 0, (size_t)NN * OC * sizeof(float), 0);
    void* denp = nullptr;
    cudaGetSymbolAddress(&denp, g_den);
    cudaMemsetAsync(denp, 0, (size_t)NN * NH * sizeof(float), 0);

    const int cvt_tot = (NN * KDIM + KDIM * NDIM) / 4;
    k_cvt<<<(cvt_tot + 255) / 256, 256>>>(x, W);

    dim3 ggrid(NDIM / 128, (NN + 127) / 128);   // (4, 157)
    k_gemm_tc<<<ggrid, 256, GEMM_SMEM>>>(att_src, att_dst);

    const int etot4 = ETOT * NH;
    k_edge_sum<<<(etot4 + 255) / 256, 256>>>(ei);

    const int nwarp = ETOT / 2;
    k_scatter<<<(nwarp * 32 + 255) / 256, 256>>>(ei, out);

    k_final<<<(NN * OC + 255) / 256, 256>>>(out, bias);
}

// round 11
// speedup vs baseline: 1.3348x; 1.0199x over previous
#include <cuda_runtime.h>
#include <cuda_fp16.h>
#include <cfloat>
#include <math.h>
#include <cstdint>
#include <mma.h>

using namespace nvcuda;

// Problem constants
#define NN   20000
#define NE   320000
#define HC   512
#define NH   4
#define OC   128
#define KDIM 512
#define NDIM 512
#define ETOT (NE + NN)   // 340000 (divisible by 4)

// -------- scratch --------
__device__ __half g_xh[(size_t)NN * KDIM];    // x, fp16
__device__ __half g_wh[(size_t)KDIM * NDIM];  // W, fp16
__device__ __half g_xlh[(size_t)NN * HC];     // projected features, fp16
__device__ __align__(16) float g_as[NN * NH];
__device__ __align__(16) float g_ad[NN * NH];
__device__ __align__(16) float g_den[NN * NH];

// ---------------- fp16 pre-conversion of x and W ----------------
__global__ void k_cvt(const float* __restrict__ x, const float* __restrict__ W) {
    const int totx = NN * KDIM / 4;
    const int totw = KDIM * NDIM / 4;
    int i = blockIdx.x * blockDim.x + threadIdx.x;
    if (i < totx) {
        float4 v = ((const float4*)x)[i];
        union { uint2 u; __half2 h[2]; } pk;
        pk.h[0] = __floats2half2_rn(v.x, v.y);
        pk.h[1] = __floats2half2_rn(v.z, v.w);
        ((uint2*)g_xh)[i] = pk.u;
    } else if (i < totx + totw) {
        int j = i - totx;
        float4 v = ((const float4*)W)[j];
        union { uint2 u; __half2 h[2]; } pk;
        pk.h[0] = __floats2half2_rn(v.x, v.y);
        pk.h[1] = __floats2half2_rn(v.z, v.w);
        ((uint2*)g_wh)[j] = pk.u;
    }
}

// ---------------- GEMM (fp16 wmma 16x16x16) + fused epilogue -------------
#define BLK_K  64
#define LDA_H  72
#define LDB_H  136
#define A_HALFS (128 * LDA_H)
#define B_HALFS (BLK_K * LDB_H)
#define STAGE_HALFS (A_HALFS + B_HALFS)
#define NSTAGE 3
#define GEMM_SMEM (NSTAGE * STAGE_HALFS * 2)
#define LDC 132

__device__ __forceinline__ uint32_t smem_u32(const void* p) {
    uint32_t a;
    asm("{ .reg .u64 t; cvta.to.shared.u64 t, %1; cvt.u32.u64 %0, t; }" : "=r"(a) : "l"(p));
    return a;
}

__global__ __launch_bounds__(256) void k_gemm_tc(const float* __restrict__ att_src,
                                                 const float* __restrict__ att_dst) {
    extern __shared__ __half smemh[];
    __half* As = smemh;
    __half* Bs = smemh + NSTAGE * A_HALFS;

    const int tid = threadIdx.x;
    const int warpId = tid >> 5;
    const int lane = tid & 31;
    const int warpM = warpId & 3;
    const int warpN = warpId >> 2;
    const int m0 = blockIdx.y * 128;
    const int n0 = blockIdx.x * 128;

    const uint32_t sA = smem_u32(As);
    const uint32_t sB = smem_u32(Bs);

    auto load_stage = [&](int kc, int buf) {
        const int k0 = kc * BLK_K;
        #pragma unroll
        for (int it = 0; it < 4; it++) {
            int id = tid + it * 256;
            int r = id >> 3, q = id & 7;
            int grow = m0 + r;
            const __half* gp = g_xh + (size_t)(grow < NN ? grow : 0) * KDIM + k0 + q * 8;
            int sz = (grow < NN) ? 16 : 0;
            uint32_t so = sA + (buf * A_HALFS + r * LDA_H + q * 8) * 2;
            asm volatile("cp.async.cg.shared.global [%0], [%1], 16, %2;"
                         :: "r"(so), "l"(gp), "r"(sz));
        }
        #pragma unroll
        for (int it = 0; it < 4; it++) {
            int id = tid + it * 256;
            int r = id >> 4, q = id & 15;
            const __half* gp = g_wh + (size_t)(k0 + r) * NDIM + n0 + q * 8;
            uint32_t so = sB + (buf * B_HALFS + r * LDB_H + q * 8) * 2;
            asm volatile("cp.async.cg.shared.global [%0], [%1], 16;"
                         :: "r"(so), "l"(gp));
        }
        asm volatile("cp.async.commit_group;" ::: "memory");
    };

    wmma::fragment<wmma::accumulator, 16, 16, 16, float> acc[2][4];
    #pragma unroll
    for (int i = 0; i < 2; i++)
        #pragma unroll
        for (int j = 0; j < 4; j++) wmma::fill_fragment(acc[i][j], 0.f);

    load_stage(0, 0);
    load_stage(1, 1);

    const int NCHUNK = KDIM / BLK_K;   // 8
    for (int kc = 0; kc < NCHUNK; kc++) {
        const int buf = kc % NSTAGE;
        if (kc + 1 < NCHUNK)
            asm volatile("cp.async.wait_group 1;" ::: "memory");
        else
            asm volatile("cp.async.wait_group 0;" ::: "memory");
        __syncthreads();
        if (kc + 2 < NCHUNK) load_stage(kc + 2, (kc + 2) % NSTAGE);

        const __half* Ab = As + buf * A_HALFS + warpM * 32 * LDA_H;
        const __half* Bb = Bs + buf * B_HALFS + warpN * 64;
        #pragma unroll
        for (int ks = 0; ks < BLK_K / 16; ks++) {
            wmma::fragment<wmma::matrix_a, 16, 16, 16, __half, wmma::row_major> af[2];
            wmma::fragment<wmma::matrix_b, 16, 16, 16, __half, wmma::row_major> bf[4];
            #pragma unroll
            for (int mt = 0; mt < 2; mt++)
                wmma::load_matrix_sync(af[mt], Ab + mt * 16 * LDA_H + ks * 16, LDA_H);
            #pragma unroll
            for (int nt = 0; nt < 4; nt++)
                wmma::load_matrix_sync(bf[nt], Bb + ks * 16 * LDB_H + nt * 16, LDB_H);
            #pragma unroll
            for (int mt = 0; mt < 2; mt++)
                #pragma unroll
                for (int nt = 0; nt < 4; nt++)
                    wmma::mma_sync(acc[mt][nt], af[mt], bf[nt], acc[mt][nt]);
        }
    }

    // -------- fused epilogue: attn halves + fp16 store --------
    __syncthreads();
    float* Cs = (float*)smemh;
    #pragma unroll
    for (int mt = 0; mt < 2; mt++)
        #pragma unroll
        for (int nt = 0; nt < 4; nt++)
            wmma::store_matrix_sync(Cs + (warpM * 32 + mt * 16) * LDC + warpN * 64 + nt * 16,
                                    acc[mt][nt], LDC, wmma::mem_row_major);
    __syncthreads();

    const int h = blockIdx.x;
    float4 sv = *(const float4*)(att_src + h * OC + lane * 4);
    float4 dv = *(const float4*)(att_dst + h * OC + lane * 4);

    #pragma unroll
    for (int r = 0; r < 16; r++) {
        int lrow = warpId * 16 + r;
        int grow = m0 + lrow;
        float4 v = *(const float4*)(Cs + lrow * LDC + lane * 4);
        float ss = v.x * sv.x + v.y * sv.y + v.z * sv.z + v.w * sv.w;
        float dd = v.x * dv.x + v.y * dv.y + v.z * dv.z + v.w * dv.w;
        #pragma unroll
        for (int o = 16; o; o >>= 1) {
            ss += __shfl_xor_sync(0xFFFFFFFFu, ss, o);
            dd += __shfl_xor_sync(0xFFFFFFFFu, dd, o);
        }
        if (grow < NN) {
            union { uint2 u; __half2 hh[2]; } pk;
            pk.hh[0] = __floats2half2_rn(v.x, v.y);
            pk.hh[1] = __floats2half2_rn(v.z, v.w);
            *(uint2*)(g_xlh + (size_t)grow * HC + h * OC + lane * 4) = pk.u;
            if (lane == 0) {
                g_as[grow * NH + h] = ss;
                g_ad[grow * NH + h] = dd;
            }
        }
    }
}

__device__ __forceinline__ float leaky(float a) { return a > 0.f ? a : 0.2f * a; }

// ---------------- segment sum of exp(alpha): thread per edge, v4 red ----
__global__ void k_edge_sum(const int* __restrict__ ei) {
    int e = blockIdx.x * blockDim.x + threadIdx.x;
    if (e >= ETOT) return;
    int src, dst;
    if (e < NE) { src = __ldg(&ei[e]); dst = __ldg(&ei[NE + e]); }
    else        { src = dst = e - NE; }
    float4 as = *(const float4*)&g_as[src * NH];
    float4 ad = *(const float4*)&g_ad[dst * NH];
    float4 v;
    v.x = __expf(leaky(as.x + ad.x));
    v.y = __expf(leaky(as.y + ad.y));
    v.z = __expf(leaky(as.z + ad.z));
    v.w = __expf(leaky(as.w + ad.w));
    float* dp = &g_den[dst * NH];
    asm volatile("red.global.add.v4.f32 [%0], {%1, %2, %3, %4};"
                 :: "l"(dp), "f"(v.x), "f"(v.y), "f"(v.z), "f"(v.w) : "memory");
}

// ---------------- weighted scatter: 4 edges per warp (fp16 gather) ------
__global__ __launch_bounds__(256) void k_scatter(const int* __restrict__ ei,
                                                 float* __restrict__ out) {
    int w    = (blockIdx.x * blockDim.x + threadIdx.x) >> 5;
    int lane = threadIdx.x & 31;
    if (w >= ETOT / 4) return;
    const int e0 = 4 * w;

    int s[4], d[4];
    #pragma unroll
    for (int j = 0; j < 4; j++) {
        int e = e0 + j;
        if (e < NE) { s[j] = __ldg(&ei[e]); d[j] = __ldg(&ei[NE + e]); }
        else        { s[j] = d[j] = e - NE; }
    }

    // lanes 0-15: one (edge, head) weight each, fully parallel
    float wt = 0.f;
    if (lane < 16) {
        int j = lane >> 2, h = lane & 3;
        float a = leaky(g_as[s[j] * NH + h] + g_ad[d[j] * NH + h]);
        wt = __expf(a) / (g_den[d[j] * NH + h] + 1e-16f);
    }

    // 16 independent 256B warp-gathers in flight
    uint2 q[4][4];
    #pragma unroll
    for (int j = 0; j < 4; j++) {
        const uint2* xr = (const uint2*)(g_xlh + (size_t)s[j] * HC);
        q[j][0] = __ldg(&xr[lane]);
        q[j][1] = __ldg(&xr[32 + lane]);
        q[j][2] = __ldg(&xr[64 + lane]);
        q[j][3] = __ldg(&xr[96 + lane]);
    }

    #pragma unroll
    for (int j = 0; j < 4; j++) {
        float4 r = make_float4(0.f, 0.f, 0.f, 0.f);
        #pragma unroll
        for (int h = 0; h < 4; h++) {
            float wh = __shfl_sync(0xFFFFFFFFu, wt, j * 4 + h);
            float2 f0 = __half22float2(*(__half2*)&q[j][h].x);
            float2 f1 = __half22float2(*(__half2*)&q[j][h].y);
            r.x += wh * f0.x; r.y += wh * f0.y; r.z += wh * f1.x; r.w += wh * f1.y;
        }
        float* dp = out + (size_t)d[j] * OC + lane * 4;
        asm volatile("red.global.add.v4.f32 [%0], {%1, %2, %3, %4};"
                     :: "l"(dp), "f"(r.x), "f"(r.y), "f"(r.z), "f"(r.w) : "memory");
    }
}

// ---------------- finalize ----------------
__global__ void k_final(float* __restrict__ out, const float* __restrict__ bias) {
    int i = blockIdx.x * blockDim.x + threadIdx.x;
    if (i >= NN * OC) return;
    float v = out[i] * 0.25f + bias[i & (OC - 1)];
    out[i] = v > 0.f ? v : expm1f(v);
}

// ========================================================================
extern "C" void kernel_launch(void* const* d_in, const int* in_sizes, int n_in,
                              void* d_out, int out_size) {
    const float* x       = (const float*)d_in[0];
    const float* W       = (const float*)d_in[1];
    const float* att_src = (const float*)d_in[2];
    const float* att_dst = (const float*)d_in[3];
    const float* bias    = (const float*)d_in[4];
    const int*   ei      = (const int*)d_in[5];
    float* out = (float*)d_out;

    cudaFuncSetAttribute(k_gemm_tc, cudaFuncAttributeMaxDynamicSharedMemorySize,
                         GEMM_SMEM);

    // zero accumulators via DMA (graph-capturable async memsets)
    cudaMemsetAsync(out, 0, (size_t)NN * OC * sizeof(float), 0);
    void* denp = nullptr;
    cudaGetSymbolAddress(&denp, g_den);
    cudaMemsetAsync(denp, 0, (size_t)NN * NH * sizeof(float), 0);

    const int cvt_tot = (NN * KDIM + KDIM * NDIM) / 4;
    k_cvt<<<(cvt_tot + 255) / 256, 256>>>(x, W);

    dim3 ggrid(NDIM / 128, (NN + 127) / 128);   // (4, 157)
    k_gemm_tc<<<ggrid, 256, GEMM_SMEM>>>(att_src, att_dst);

    k_edge_sum<<<(ETOT + 255) / 256, 256>>>(ei);

    const int nwarp = ETOT / 4;
    k_scatter<<<(nwarp * 32 + 255) / 256, 256>>>(ei, out);

    k_final<<<(NN * OC + 255) / 256, 256>>>(out, bias);
}